// round 13
// baseline (speedup 1.0000x reference)
#include <cuda_runtime.h>

typedef unsigned long long ull;

#define NPOINTS 32768
#define HW      4096
#define NCODES  8192
#define NSLICE  32
#define KSLICE  (NCODES / NSLICE)   // 256 codes per slice
#define PAIRS   (KSLICE / 2)        // 128 code-pairs per slice
#define T1      64                  // threads per CTA (2 warps)
#define PPT     4                   // points per thread
#define PGROUPS (NPOINTS / (T1 * PPT))  // 128  -> grid = 4096 CTAs
#define FT      256                 // finalize threads per block
#define FBLOCKS (NPOINTS * 2 / FT)  // 256 finalize blocks (2 threads/point)

// Scratch (device globals — no allocation allowed in kernel_launch)
// POINT-MAJOR: g_bi[p*NSLICE + sl] -> finalize reads are 256B-contiguous/point
__device__ float2 g_bi[NPOINTS * NSLICE];
__device__ float  g_partial[FBLOCKS];
__device__ int    g_ctr;                   // threadfence-reduction counter

// ---- packed f32x2 helpers (sm_103a); per-lane IEEE rn, same as scalar ----
__device__ __forceinline__ ull fma2(ull a, ull b, ull c) {
    ull d;
    asm("fma.rn.f32x2 %0, %1, %2, %3;" : "=l"(d) : "l"(a), "l"(b), "l"(c));
    return d;
}
__device__ __forceinline__ ull add2(ull a, ull b) {
    ull d;
    asm("add.rn.f32x2 %0, %1, %2;" : "=l"(d) : "l"(a), "l"(b));
    return d;
}
__device__ __forceinline__ ull mul2(ull a, ull b) {
    ull d;
    asm("mul.rn.f32x2 %0, %1, %2;" : "=l"(d) : "l"(a), "l"(b));
    return d;
}
__device__ __forceinline__ ull pack2(float lo, float hi) {
    ull d;
    asm("mov.b64 %0, {%1, %2};" : "=l"(d) : "f"(lo), "f"(hi));
    return d;
}
__device__ __forceinline__ void unpack2(ull v, float& lo, float& hi) {
    asm("mov.b64 {%0, %1}, %2;" : "=f"(lo), "=f"(hi) : "l"(v));
}

// Reference fp32 1x1-conv einsum + bias, XLA/cuBLAS association:
//   dot = ascending-k FFMA chain starting from x0*w0; z = dot + b (bias LAST).
__device__ __forceinline__ void compute_z(
    const float* __restrict__ zin, const float* w /*16*/,
    const float* bb /*4*/, int p, float z[4])
{
    int b = p >> 12, hw = p & (HW - 1);
    const float* base = zin + b * (4 * HW) + hw;
    float x0 = base[0], x1 = base[HW], x2 = base[2 * HW], x3 = base[3 * HW];
#pragma unroll
    for (int o = 0; o < 4; o++) {
        float acc = __fmul_rn(x0, w[o * 4 + 0]);
        acc = __fmaf_rn(x1, w[o * 4 + 1], acc);
        acc = __fmaf_rn(x2, w[o * 4 + 2], acc);
        acc = __fmaf_rn(x3, w[o * 4 + 3], acc);
        z[o] = __fadd_rn(acc, bb[o]);
    }
}

// sum of squares, XLA style: elementwise multiply THEN sequential add (no FMA)
__device__ __forceinline__ float sumsq4(float a, float b, float c, float d) {
    float m0 = __fmul_rn(a, a), m1 = __fmul_rn(b, b);
    float m2 = __fmul_rn(c, c), m3 = __fmul_rn(d, d);
    return __fadd_rn(__fadd_rn(__fadd_rn(m0, m1), m2), m3);
}

// d2 pair for pair-record q, given zn (=-2z packed) and szz (packed):
//   acc == -2*dot with reference per-step roundings; d2 = (szz-2dot)+scc
__device__ __forceinline__ ull d2_pair(const ull* q, const ull zn[4], ull szz2) {
    ull acc = mul2(zn[0], q[0]);
    acc = fma2(zn[1], q[1], acc);
    acc = fma2(zn[2], q[2], acc);
    acc = fma2(zn[3], q[3], acc);
    ull t = add2(szz2, acc);
    return add2(t, q[4]);
}

// ============================================================================
// Kernel 1: per (point-group, code-slice) CTA — scan 256 codes for 256 points.
// Scan tracks only (best value, best PAIR): lane-reduced argmin; winning lane
// recovered post-loop by recomputing that single pair's d2. Tie semantics
// exact: strict < keeps earliest pair; even lane preferred on equality.
// smem pair layout (12 floats = 48B): [2d+ln] = c_{2pr+ln}[d], [8+ln] = ||c||^2
// ============================================================================
__global__ __launch_bounds__(T1) void vq_search(
    const float* __restrict__ zin,   // [8,4,64,64]
    const float* __restrict__ Wm,    // [4,4]
    const float* __restrict__ bv,    // [4]
    const float* __restrict__ cb)    // [8192,4]
{
    __shared__ float s[PAIRS * 12];
    __shared__ float wq[16], bb[4];
    const int tid   = threadIdx.x;
    const int pg    = blockIdx.x;   // 0..127
    const int slice = blockIdx.y;   // 0..31
    const int k0    = slice * KSLICE;

    if (tid < 16) wq[tid] = __ldg(Wm + tid);
    if (tid < 4)  bb[tid] = __ldg(bv + tid);

    // Build codebook slice + fp32 |c|^2 (mul-then-add order) in smem
#pragma unroll
    for (int kk = tid; kk < KSLICE; kk += T1) {
        float4 c = ((const float4*)cb)[k0 + kk];
        int pr = kk >> 1, ln = kk & 1;
        float* d = s + pr * 12;
        d[0 + ln] = c.x;
        d[2 + ln] = c.y;
        d[4 + ln] = c.z;
        d[6 + ln] = c.w;
        d[8 + ln] = sumsq4(c.x, c.y, c.z, c.w);
    }
    __syncthreads();

    ull zn[PPT][4];   // -2*z_d duplicated in both halves (exact scaling)
    ull szz2[PPT];    // ||z||^2 duplicated
#pragma unroll
    for (int j = 0; j < PPT; j++) {
        int p = pg * (T1 * PPT) + j * T1 + tid;  // coalesced over tid
        float z[4];
        compute_z(zin, wq, bb, p, z);
        float szz = sumsq4(z[0], z[1], z[2], z[3]);
        szz2[j] = pack2(szz, szz);
#pragma unroll
        for (int o = 0; o < 4; o++) {
            float m = -2.0f * z[o];   // exact (power-of-two scale + negate)
            zn[j][o] = pack2(m, m);
        }
    }

    float best[PPT];
    int   bpr[PPT];
#pragma unroll
    for (int j = 0; j < PPT; j++) { best[j] = 3.4e38f; bpr[j] = 0; }

#pragma unroll 8
    for (int pr = 0; pr < PAIRS; ++pr) {
        const ull* q = (const ull*)(s + pr * 12);  // 48B stride, 16B aligned
        ull m0 = q[0], m1 = q[1], m2 = q[2], m3 = q[3], cc = q[4];
#pragma unroll
        for (int j = 0; j < PPT; j++) {
            ull acc = mul2(zn[j][0], m0);
            acc = fma2(zn[j][1], m1, acc);
            acc = fma2(zn[j][2], m2, acc);
            acc = fma2(zn[j][3], m3, acc);
            ull t  = add2(szz2[j], acc);   // rn(szz - 2*dot)
            ull d2 = add2(t, cc);          // + ||c||^2
            float s0, s1;
            unpack2(d2, s0, s1);
            // lane-reduce then pair-track: 4 ALU ops total
            float pm  = fminf(s0, s1);
            bool  imp = (pm < best[j]);        // strict: earliest pair on ties
            best[j] = fminf(best[j], pm);
            bpr[j]  = imp ? pr : bpr[j];
        }
    }

    // Recover winning lane per point (one pair recompute, amortized ~1%)
#pragma unroll
    for (int j = 0; j < PPT; j++) {
        int p = pg * (T1 * PPT) + j * T1 + tid;
        const ull* q = (const ull*)(s + bpr[j] * 12);
        float s0, s1;
        unpack2(d2_pair(q, zn[j], szz2[j]), s0, s1);
        // even lane preferred on equality (lower k = first occurrence)
        int lane = (__float_as_int(s0) == __float_as_int(best[j])) ? 0 : 1;
        int idx  = k0 + 2 * bpr[j] + lane;
        g_bi[p * NSLICE + slice] = make_float2(best[j], __int_as_float(idx));
    }
}

// ============================================================================
// Kernel 2: TWO threads per point; each merges 16 slices via 8 coalesced
// LDG.128 (point-major layout), halves combined with one shfl_xor.
// h0 (lower slices) wins ties: cross-half accept only on strict <.
// Then gather code, write latent (z + (zq - z)), loss partials; last block
// does the final fixed-tree loss reduction (threadfence-reduction).
// ============================================================================
__global__ __launch_bounds__(FT) void vq_finalize(
    const float* __restrict__ zin,
    const float* __restrict__ Wm,
    const float* __restrict__ bv,
    const float* __restrict__ cb,
    float* __restrict__ out,
    int loss_idx)
{
    __shared__ float wq[16], bb[4];
    __shared__ float wsum[FT / 32];
    __shared__ bool  islast;
    if (threadIdx.x < 16) wq[threadIdx.x] = __ldg(Wm + threadIdx.x);
    if (threadIdx.x < 4)  bb[threadIdx.x] = __ldg(bv + threadIdx.x);
    __syncthreads();

    const int gt = blockIdx.x * FT + threadIdx.x;
    const int p  = gt >> 1;          // point
    const int h  = gt & 1;           // half: 0 -> slices 0..15, 1 -> 16..31

    // merge 16 slices: 8 independent LDG.128 (each = 2 records)
    float bestv = 3.4e38f;
    int   idx   = 0;
    const float4* base4 = (const float4*)(g_bi + p * NSLICE + h * 16);
#pragma unroll
    for (int i = 0; i < 8; i++) {
        float4 v = base4[i];
        if (v.x < bestv) { bestv = v.x; idx = __float_as_int(v.y); }
        if (v.z < bestv) { bestv = v.z; idx = __float_as_int(v.w); }
    }
    // combine halves: h0 keeps ties (ascending-slice first-occurrence)
    float ov = __shfl_xor_sync(0xffffffffu, bestv, 1);
    int   oi = __shfl_xor_sync(0xffffffffu, idx, 1);

    float acc = 0.f;
    if (h == 0) {
        if (ov < bestv) { bestv = ov; idx = oi; }   // strict: h0 wins ties

        float z[4];
        compute_z(zin, wq, bb, p, z);

        float4 c = ((const float4*)cb)[idx];
        const int b  = p >> 12;
        const int hw = p & (HW - 1);
        float* ob = out + b * (4 * HW) + hw;
        // straight-through: z + (zq - z), two roundings, as in the reference
        float r0 = __fadd_rn(c.x, -z[0]);
        float r1 = __fadd_rn(c.y, -z[1]);
        float r2 = __fadd_rn(c.z, -z[2]);
        float r3 = __fadd_rn(c.w, -z[3]);
        ob[0]      = __fadd_rn(z[0], r0);
        ob[HW]     = __fadd_rn(z[1], r1);
        ob[2 * HW] = __fadd_rn(z[2], r2);
        ob[3 * HW] = __fadd_rn(z[3], r3);

        acc = sumsq4(r0, r1, r2, r3);
    }

    // warp shuffle reduce, then one smem round (deterministic order)
#pragma unroll
    for (int o = 16; o > 0; o >>= 1)
        acc += __shfl_down_sync(0xffffffffu, acc, o);
    if ((threadIdx.x & 31) == 0) wsum[threadIdx.x >> 5] = acc;
    __syncthreads();
    if (threadIdx.x == 0) {
        float t = 0.f;
#pragma unroll
        for (int w = 0; w < FT / 32; w++) t += wsum[w];
        g_partial[blockIdx.x] = t;
        __threadfence();
        islast = (atomicAdd(&g_ctr, 1) == FBLOCKS - 1);
    }
    __syncthreads();

    if (islast) {
        // final reduction over FBLOCKS=256 partials (fixed tree order)
        __shared__ float red[FBLOCKS];
        red[threadIdx.x] = g_partial[threadIdx.x];
        __syncthreads();
#pragma unroll
        for (int st = FBLOCKS / 2; st > 0; st >>= 1) {
            if (threadIdx.x < st) red[threadIdx.x] += red[threadIdx.x + st];
            __syncthreads();
        }
        if (threadIdx.x == 0) {
            out[loss_idx] = red[0] * (1.25f / (float)(NPOINTS * 4));
            g_ctr = 0;   // reset for next graph replay (deterministic)
        }
    }
}

extern "C" void kernel_launch(void* const* d_in, const int* in_sizes, int n_in,
                              void* d_out, int out_size)
{
    const float* zin = (const float*)d_in[0];  // z_e_in [8,4,64,64]
    const float* Wm  = (const float*)d_in[1];  // pq_w [4,4]
    const float* bv  = (const float*)d_in[2];  // pq_b [4]
    const float* cb  = (const float*)d_in[3];  // codebook [8192,4]
    float* out = (float*)d_out;

    dim3 g1(PGROUPS, NSLICE);
    vq_search<<<g1, T1>>>(zin, Wm, bv, cb);
    vq_finalize<<<FBLOCKS, FT>>>(zin, Wm, bv, cb, out, out_size - 1);
}

// round 15
// speedup vs baseline: 1.0535x; 1.0535x over previous
#include <cuda_runtime.h>

typedef unsigned long long ull;

#define NPOINTS 32768
#define HW      4096
#define NCODES  8192
#define NSLICE  32
#define KSLICE  (NCODES / NSLICE)   // 256 codes per slice
#define PAIRS   (KSLICE / 2)        // 128 code-pairs per slice
#define T1      64                  // threads per CTA (2 warps)
#define PPT     4                   // points per thread
#define PGROUPS (NPOINTS / (T1 * PPT))  // 128  -> grid = 4096 CTAs
#define FT      256                 // finalize threads per block
#define FBLOCKS (NPOINTS / FT)      // 128 finalize blocks

// Scratch (device globals — no allocation allowed in kernel_launch)
__device__ ull   g_key[NPOINTS];    // (monotonic d2 bits << 32) | idx
__device__ float g_partial[FBLOCKS];
__device__ int   g_ctr;             // threadfence-reduction counter

// ---- packed f32x2 helpers (sm_103a); per-lane IEEE rn, same as scalar ----
__device__ __forceinline__ ull fma2(ull a, ull b, ull c) {
    ull d;
    asm("fma.rn.f32x2 %0, %1, %2, %3;" : "=l"(d) : "l"(a), "l"(b), "l"(c));
    return d;
}
__device__ __forceinline__ ull add2(ull a, ull b) {
    ull d;
    asm("add.rn.f32x2 %0, %1, %2;" : "=l"(d) : "l"(a), "l"(b));
    return d;
}
__device__ __forceinline__ ull mul2(ull a, ull b) {
    ull d;
    asm("mul.rn.f32x2 %0, %1, %2;" : "=l"(d) : "l"(a), "l"(b));
    return d;
}
__device__ __forceinline__ ull pack2(float lo, float hi) {
    ull d;
    asm("mov.b64 %0, {%1, %2};" : "=l"(d) : "f"(lo), "f"(hi));
    return d;
}
__device__ __forceinline__ void unpack2(ull v, float& lo, float& hi) {
    asm("mov.b64 {%0, %1}, %2;" : "=f"(lo), "=f"(hi) : "l"(v));
}

// total-order map: float bits -> u32 where smaller float => smaller uint
__device__ __forceinline__ unsigned fmono(float x) {
    unsigned b = __float_as_uint(x);
    return (b & 0x80000000u) ? ~b : (b | 0x80000000u);
}

// Reference fp32 1x1-conv einsum + bias, XLA/cuBLAS association:
//   dot = ascending-k FFMA chain starting from x0*w0; z = dot + b (bias LAST).
__device__ __forceinline__ void compute_z(
    const float* __restrict__ zin, const float* w /*16*/,
    const float* bb /*4*/, int p, float z[4])
{
    int b = p >> 12, hw = p & (HW - 1);
    const float* base = zin + b * (4 * HW) + hw;
    float x0 = base[0], x1 = base[HW], x2 = base[2 * HW], x3 = base[3 * HW];
#pragma unroll
    for (int o = 0; o < 4; o++) {
        float acc = __fmul_rn(x0, w[o * 4 + 0]);
        acc = __fmaf_rn(x1, w[o * 4 + 1], acc);
        acc = __fmaf_rn(x2, w[o * 4 + 2], acc);
        acc = __fmaf_rn(x3, w[o * 4 + 3], acc);
        z[o] = __fadd_rn(acc, bb[o]);
    }
}

// sum of squares, XLA style: elementwise multiply THEN sequential add (no FMA)
__device__ __forceinline__ float sumsq4(float a, float b, float c, float d) {
    float m0 = __fmul_rn(a, a), m1 = __fmul_rn(b, b);
    float m2 = __fmul_rn(c, c), m3 = __fmul_rn(d, d);
    return __fadd_rn(__fadd_rn(__fadd_rn(m0, m1), m2), m3);
}

// d2 pair for pair-record q, given zn (=-2z packed) and szz (packed):
//   acc == -2*dot with reference per-step roundings; d2 = (szz-2dot)+scc
__device__ __forceinline__ ull d2_pair(const ull* q, const ull zn[4], ull szz2) {
    ull acc = mul2(zn[0], q[0]);
    acc = fma2(zn[1], q[1], acc);
    acc = fma2(zn[2], q[2], acc);
    acc = fma2(zn[3], q[3], acc);
    ull t = add2(szz2, acc);
    return add2(t, q[4]);
}

// ============================================================================
// Kernel 0: init keys (and counter) for this launch — graph-replay safe.
// ============================================================================
__global__ __launch_bounds__(256) void vq_init()
{
    int i = blockIdx.x * 256 + threadIdx.x;
    ull* k = g_key + i * 4;   // 32 blocks * 256 threads * 4 = 32768
    k[0] = ~0ull; k[1] = ~0ull; k[2] = ~0ull; k[3] = ~0ull;
    if (i == 0) g_ctr = 0;
}

// ============================================================================
// Kernel 1: per (point-group, code-slice) CTA — scan 256 codes for 256 points.
// Lane-reduced argmin scan; winning lane recovered post-loop. Result merged
// across slices via atomicMin on a monotonic (d2,idx) key — min is
// commutative/associative => deterministic under any atomic order, and
// (bits,idx) ordering gives EXACT first-occurrence argmin tie semantics.
// smem pair layout (12 floats = 48B): [2d+ln] = c_{2pr+ln}[d], [8+ln] = ||c||^2
// ============================================================================
__global__ __launch_bounds__(T1) void vq_search(
    const float* __restrict__ zin,   // [8,4,64,64]
    const float* __restrict__ Wm,    // [4,4]
    const float* __restrict__ bv,    // [4]
    const float* __restrict__ cb)    // [8192,4]
{
    __shared__ float s[PAIRS * 12];
    __shared__ float wq[16], bb[4];
    const int tid   = threadIdx.x;
    const int pg    = blockIdx.x;   // 0..127
    const int slice = blockIdx.y;   // 0..31
    const int k0    = slice * KSLICE;

    if (tid < 16) wq[tid] = __ldg(Wm + tid);
    if (tid < 4)  bb[tid] = __ldg(bv + tid);

    // Build codebook slice + fp32 |c|^2 (mul-then-add order) in smem
#pragma unroll
    for (int kk = tid; kk < KSLICE; kk += T1) {
        float4 c = ((const float4*)cb)[k0 + kk];
        int pr = kk >> 1, ln = kk & 1;
        float* d = s + pr * 12;
        d[0 + ln] = c.x;
        d[2 + ln] = c.y;
        d[4 + ln] = c.z;
        d[6 + ln] = c.w;
        d[8 + ln] = sumsq4(c.x, c.y, c.z, c.w);
    }
    __syncthreads();

    ull zn[PPT][4];   // -2*z_d duplicated in both halves (exact scaling)
    ull szz2[PPT];    // ||z||^2 duplicated
#pragma unroll
    for (int j = 0; j < PPT; j++) {
        int p = pg * (T1 * PPT) + j * T1 + tid;  // coalesced over tid
        float z[4];
        compute_z(zin, wq, bb, p, z);
        float szz = sumsq4(z[0], z[1], z[2], z[3]);
        szz2[j] = pack2(szz, szz);
#pragma unroll
        for (int o = 0; o < 4; o++) {
            float m = -2.0f * z[o];   // exact (power-of-two scale + negate)
            zn[j][o] = pack2(m, m);
        }
    }

    float best[PPT];
    int   bpr[PPT];
#pragma unroll
    for (int j = 0; j < PPT; j++) { best[j] = 3.4e38f; bpr[j] = 0; }

#pragma unroll 8
    for (int pr = 0; pr < PAIRS; ++pr) {
        const ull* q = (const ull*)(s + pr * 12);  // 48B stride, 16B aligned
        ull m0 = q[0], m1 = q[1], m2 = q[2], m3 = q[3], cc = q[4];
#pragma unroll
        for (int j = 0; j < PPT; j++) {
            ull acc = mul2(zn[j][0], m0);
            acc = fma2(zn[j][1], m1, acc);
            acc = fma2(zn[j][2], m2, acc);
            acc = fma2(zn[j][3], m3, acc);
            ull t  = add2(szz2[j], acc);   // rn(szz - 2*dot)
            ull d2 = add2(t, cc);          // + ||c||^2
            float s0, s1;
            unpack2(d2, s0, s1);
            // lane-reduce then pair-track: 4 ALU ops total
            float pm  = fminf(s0, s1);
            bool  imp = (pm < best[j]);        // strict: earliest pair on ties
            best[j] = fminf(best[j], pm);
            bpr[j]  = imp ? pr : bpr[j];
        }
    }

    // Recover winning lane, publish via atomicMin on monotonic key
#pragma unroll
    for (int j = 0; j < PPT; j++) {
        int p = pg * (T1 * PPT) + j * T1 + tid;
        const ull* q = (const ull*)(s + bpr[j] * 12);
        float s0, s1;
        unpack2(d2_pair(q, zn[j], szz2[j]), s0, s1);
        // even lane preferred on equality (lower k = first occurrence)
        int lane = (__float_as_int(s0) == __float_as_int(best[j])) ? 0 : 1;
        unsigned idx = (unsigned)(k0 + 2 * bpr[j] + lane);
        ull key = ((ull)fmono(best[j]) << 32) | idx;
        atomicMin(&g_key[p], key);   // RED.MIN.U64, spread addresses
    }
}

// ============================================================================
// Kernel 2: per-point key load (coalesced 8B), decode idx, gather code,
// write latent (z + (zq - z)), loss partials; last block does the final
// fixed-tree loss reduction (threadfence-reduction, deterministic).
// ============================================================================
__global__ __launch_bounds__(FT) void vq_finalize(
    const float* __restrict__ zin,
    const float* __restrict__ Wm,
    const float* __restrict__ bv,
    const float* __restrict__ cb,
    float* __restrict__ out,
    int loss_idx)
{
    __shared__ float wq[16], bb[4];
    __shared__ float wsum[FT / 32];
    __shared__ bool  islast;
    if (threadIdx.x < 16) wq[threadIdx.x] = __ldg(Wm + threadIdx.x);
    if (threadIdx.x < 4)  bb[threadIdx.x] = __ldg(bv + threadIdx.x);
    __syncthreads();

    const int p  = blockIdx.x * FT + threadIdx.x;
    const int b  = p >> 12;
    const int hw = p & (HW - 1);

    int idx = (int)(unsigned)(g_key[p] & 0xFFFFFFFFull);

    float z[4];
    compute_z(zin, wq, bb, p, z);

    float4 c = ((const float4*)cb)[idx];
    float* ob = out + b * (4 * HW) + hw;
    // straight-through: z + (zq - z), two roundings, as in the reference
    float r0 = __fadd_rn(c.x, -z[0]);
    float r1 = __fadd_rn(c.y, -z[1]);
    float r2 = __fadd_rn(c.z, -z[2]);
    float r3 = __fadd_rn(c.w, -z[3]);
    ob[0]      = __fadd_rn(z[0], r0);
    ob[HW]     = __fadd_rn(z[1], r1);
    ob[2 * HW] = __fadd_rn(z[2], r2);
    ob[3 * HW] = __fadd_rn(z[3], r3);

    float acc = sumsq4(r0, r1, r2, r3);

    // warp shuffle reduce, then one smem round (deterministic order)
#pragma unroll
    for (int o = 16; o > 0; o >>= 1)
        acc += __shfl_down_sync(0xffffffffu, acc, o);
    if ((threadIdx.x & 31) == 0) wsum[threadIdx.x >> 5] = acc;
    __syncthreads();
    if (threadIdx.x == 0) {
        float t = 0.f;
#pragma unroll
        for (int w = 0; w < FT / 32; w++) t += wsum[w];
        g_partial[blockIdx.x] = t;
        __threadfence();
        islast = (atomicAdd(&g_ctr, 1) == FBLOCKS - 1);
    }
    __syncthreads();

    if (islast) {
        // final reduction over FBLOCKS=128 partials (fixed tree order)
        // NOTE: red[] has FBLOCKS entries but the block has FT threads —
        // every access MUST be guarded by threadIdx.x < bound (R14 bug).
        __shared__ float red[FBLOCKS];
        if (threadIdx.x < FBLOCKS) red[threadIdx.x] = g_partial[threadIdx.x];
        __syncthreads();
#pragma unroll
        for (int st = FBLOCKS / 2; st > 0; st >>= 1) {
            if (threadIdx.x < st) red[threadIdx.x] += red[threadIdx.x + st];
            __syncthreads();
        }
        if (threadIdx.x == 0)
            out[loss_idx] = red[0] * (1.25f / (float)(NPOINTS * 4));
    }
}

extern "C" void kernel_launch(void* const* d_in, const int* in_sizes, int n_in,
                              void* d_out, int out_size)
{
    const float* zin = (const float*)d_in[0];  // z_e_in [8,4,64,64]
    const float* Wm  = (const float*)d_in[1];  // pq_w [4,4]
    const float* bv  = (const float*)d_in[2];  // pq_b [4]
    const float* cb  = (const float*)d_in[3];  // codebook [8192,4]
    float* out = (float*)d_out;

    vq_init<<<32, 256>>>();
    dim3 g1(PGROUPS, NSLICE);
    vq_search<<<g1, T1>>>(zin, Wm, bv, cb);
    vq_finalize<<<FBLOCKS, FT>>>(zin, Wm, bv, cb, out, out_size - 1);
}

// round 16
// speedup vs baseline: 1.0909x; 1.0355x over previous
#include <cuda_runtime.h>

typedef unsigned long long ull;

#define NPOINTS 32768
#define HW      4096
#define NCODES  8192
#define NSLICE  32
#define KSLICE  (NCODES / NSLICE)   // 256 codes per slice
#define PAIRS   (KSLICE / 2)        // 128 code-pairs per slice
#define T1      64                  // threads per CTA (2 warps)
#define PPT     4                   // points per thread
#define PGROUPS (NPOINTS / (T1 * PPT))  // 128  -> grid = 4096 CTAs
#define FT      256                 // finalize threads per block
#define FBLOCKS (NPOINTS / FT)      // 128 finalize blocks

// Scratch (device globals — zero-initialized at module load; no allocation
// allowed in kernel_launch). INVARIANT: g_key == all-zero and g_ctr == 0 at
// every kernel_launch entry; vq_finalize restores both for the next replay.
__device__ ull   g_key[NPOINTS];    // ~((monotonic d2 bits << 32) | idx); 0 = empty
__device__ float g_partial[FBLOCKS];
__device__ int   g_ctr;             // threadfence-reduction counter

// ---- packed f32x2 helpers (sm_103a); per-lane IEEE rn, same as scalar ----
__device__ __forceinline__ ull fma2(ull a, ull b, ull c) {
    ull d;
    asm("fma.rn.f32x2 %0, %1, %2, %3;" : "=l"(d) : "l"(a), "l"(b), "l"(c));
    return d;
}
__device__ __forceinline__ ull add2(ull a, ull b) {
    ull d;
    asm("add.rn.f32x2 %0, %1, %2;" : "=l"(d) : "l"(a), "l"(b));
    return d;
}
__device__ __forceinline__ ull mul2(ull a, ull b) {
    ull d;
    asm("mul.rn.f32x2 %0, %1, %2;" : "=l"(d) : "l"(a), "l"(b));
    return d;
}
__device__ __forceinline__ ull pack2(float lo, float hi) {
    ull d;
    asm("mov.b64 %0, {%1, %2};" : "=l"(d) : "f"(lo), "f"(hi));
    return d;
}
__device__ __forceinline__ void unpack2(ull v, float& lo, float& hi) {
    asm("mov.b64 {%0, %1}, %2;" : "=f"(lo), "=f"(hi) : "l"(v));
}

// total-order map: float bits -> u32 where smaller float => smaller uint
__device__ __forceinline__ unsigned fmono(float x) {
    unsigned b = __float_as_uint(x);
    return (b & 0x80000000u) ? ~b : (b | 0x80000000u);
}

// Reference fp32 1x1-conv einsum + bias, XLA/cuBLAS association:
//   dot = ascending-k FFMA chain starting from x0*w0; z = dot + b (bias LAST).
__device__ __forceinline__ void compute_z(
    const float* __restrict__ zin, const float* w /*16*/,
    const float* bb /*4*/, int p, float z[4])
{
    int b = p >> 12, hw = p & (HW - 1);
    const float* base = zin + b * (4 * HW) + hw;
    float x0 = base[0], x1 = base[HW], x2 = base[2 * HW], x3 = base[3 * HW];
#pragma unroll
    for (int o = 0; o < 4; o++) {
        float acc = __fmul_rn(x0, w[o * 4 + 0]);
        acc = __fmaf_rn(x1, w[o * 4 + 1], acc);
        acc = __fmaf_rn(x2, w[o * 4 + 2], acc);
        acc = __fmaf_rn(x3, w[o * 4 + 3], acc);
        z[o] = __fadd_rn(acc, bb[o]);
    }
}

// sum of squares, XLA style: elementwise multiply THEN sequential add (no FMA)
__device__ __forceinline__ float sumsq4(float a, float b, float c, float d) {
    float m0 = __fmul_rn(a, a), m1 = __fmul_rn(b, b);
    float m2 = __fmul_rn(c, c), m3 = __fmul_rn(d, d);
    return __fadd_rn(__fadd_rn(__fadd_rn(m0, m1), m2), m3);
}

// d2 pair for pair-record q, given zn (=-2z packed) and szz (packed):
//   acc == -2*dot with reference per-step roundings; d2 = (szz-2dot)+scc
__device__ __forceinline__ ull d2_pair(const ull* q, const ull zn[4], ull szz2) {
    ull acc = mul2(zn[0], q[0]);
    acc = fma2(zn[1], q[1], acc);
    acc = fma2(zn[2], q[2], acc);
    acc = fma2(zn[3], q[3], acc);
    ull t = add2(szz2, acc);
    return add2(t, q[4]);
}

// ============================================================================
// Kernel 1: per (point-group, code-slice) CTA — scan 256 codes for 256 points.
// Lane-reduced argmin scan; winning lane recovered post-loop. Cross-slice
// merge via atomicMax on the INVERTED monotonic key:
//   key' = ~((fb(d2) << 32) | idx);   max key' == min (d2, idx)
// 0 is the identity (no real key' is 0: idx < 8192), matching zero-init —
// no init kernel needed. Max is commutative/associative => deterministic.
// Smaller idx wins on equal d2 bits => exact first-occurrence argmin.
// smem pair layout (12 floats = 48B): [2d+ln] = c_{2pr+ln}[d], [8+ln] = ||c||^2
// ============================================================================
__global__ __launch_bounds__(T1) void vq_search(
    const float* __restrict__ zin,   // [8,4,64,64]
    const float* __restrict__ Wm,    // [4,4]
    const float* __restrict__ bv,    // [4]
    const float* __restrict__ cb)    // [8192,4]
{
    __shared__ float s[PAIRS * 12];
    __shared__ float wq[16], bb[4];
    const int tid   = threadIdx.x;
    const int pg    = blockIdx.x;   // 0..127
    const int slice = blockIdx.y;   // 0..31
    const int k0    = slice * KSLICE;

    if (tid < 16) wq[tid] = __ldg(Wm + tid);
    if (tid < 4)  bb[tid] = __ldg(bv + tid);

    // Build codebook slice + fp32 |c|^2 (mul-then-add order) in smem
#pragma unroll
    for (int kk = tid; kk < KSLICE; kk += T1) {
        float4 c = ((const float4*)cb)[k0 + kk];
        int pr = kk >> 1, ln = kk & 1;
        float* d = s + pr * 12;
        d[0 + ln] = c.x;
        d[2 + ln] = c.y;
        d[4 + ln] = c.z;
        d[6 + ln] = c.w;
        d[8 + ln] = sumsq4(c.x, c.y, c.z, c.w);
    }
    __syncthreads();

    ull zn[PPT][4];   // -2*z_d duplicated in both halves (exact scaling)
    ull szz2[PPT];    // ||z||^2 duplicated
#pragma unroll
    for (int j = 0; j < PPT; j++) {
        int p = pg * (T1 * PPT) + j * T1 + tid;  // coalesced over tid
        float z[4];
        compute_z(zin, wq, bb, p, z);
        float szz = sumsq4(z[0], z[1], z[2], z[3]);
        szz2[j] = pack2(szz, szz);
#pragma unroll
        for (int o = 0; o < 4; o++) {
            float m = -2.0f * z[o];   // exact (power-of-two scale + negate)
            zn[j][o] = pack2(m, m);
        }
    }

    float best[PPT];
    int   bpr[PPT];
#pragma unroll
    for (int j = 0; j < PPT; j++) { best[j] = 3.4e38f; bpr[j] = 0; }

#pragma unroll 8
    for (int pr = 0; pr < PAIRS; ++pr) {
        const ull* q = (const ull*)(s + pr * 12);  // 48B stride, 16B aligned
        ull m0 = q[0], m1 = q[1], m2 = q[2], m3 = q[3], cc = q[4];
#pragma unroll
        for (int j = 0; j < PPT; j++) {
            ull acc = mul2(zn[j][0], m0);
            acc = fma2(zn[j][1], m1, acc);
            acc = fma2(zn[j][2], m2, acc);
            acc = fma2(zn[j][3], m3, acc);
            ull t  = add2(szz2[j], acc);   // rn(szz - 2*dot)
            ull d2 = add2(t, cc);          // + ||c||^2
            float s0, s1;
            unpack2(d2, s0, s1);
            // lane-reduce then pair-track: 4 ALU ops total
            float pm  = fminf(s0, s1);
            bool  imp = (pm < best[j]);        // strict: earliest pair on ties
            best[j] = fminf(best[j], pm);
            bpr[j]  = imp ? pr : bpr[j];
        }
    }

    // Recover winning lane, publish via atomicMax on inverted key
#pragma unroll
    for (int j = 0; j < PPT; j++) {
        int p = pg * (T1 * PPT) + j * T1 + tid;
        const ull* q = (const ull*)(s + bpr[j] * 12);
        float s0, s1;
        unpack2(d2_pair(q, zn[j], szz2[j]), s0, s1);
        // even lane preferred on equality (lower k = first occurrence)
        int lane = (__float_as_int(s0) == __float_as_int(best[j])) ? 0 : 1;
        unsigned idx = (unsigned)(k0 + 2 * bpr[j] + lane);
        ull key = ~(((ull)fmono(best[j]) << 32) | idx);
        atomicMax(&g_key[p], key);   // RED.MAX.U64, spread addresses
    }
}

// ============================================================================
// Kernel 2: per-point key load (coalesced 8B), decode idx, RESET key to 0
// (restores the zero-init invariant for the next graph replay), gather code,
// write latent (z + (zq - z)), loss partials; last block does the final
// fixed-tree loss reduction (threadfence-reduction) and resets g_ctr.
// ============================================================================
__global__ __launch_bounds__(FT) void vq_finalize(
    const float* __restrict__ zin,
    const float* __restrict__ Wm,
    const float* __restrict__ bv,
    const float* __restrict__ cb,
    float* __restrict__ out,
    int loss_idx)
{
    __shared__ float wq[16], bb[4];
    __shared__ float wsum[FT / 32];
    __shared__ bool  islast;
    if (threadIdx.x < 16) wq[threadIdx.x] = __ldg(Wm + threadIdx.x);
    if (threadIdx.x < 4)  bb[threadIdx.x] = __ldg(bv + threadIdx.x);
    __syncthreads();

    const int p  = blockIdx.x * FT + threadIdx.x;
    const int b  = p >> 12;
    const int hw = p & (HW - 1);

    ull keyp = g_key[p];
    g_key[p] = 0;                    // restore invariant for next replay
    int idx = (int)(unsigned)((~keyp) & 0xFFFFFFFFull);

    float z[4];
    compute_z(zin, wq, bb, p, z);

    float4 c = ((const float4*)cb)[idx];
    float* ob = out + b * (4 * HW) + hw;
    // straight-through: z + (zq - z), two roundings, as in the reference
    float r0 = __fadd_rn(c.x, -z[0]);
    float r1 = __fadd_rn(c.y, -z[1]);
    float r2 = __fadd_rn(c.z, -z[2]);
    float r3 = __fadd_rn(c.w, -z[3]);
    ob[0]      = __fadd_rn(z[0], r0);
    ob[HW]     = __fadd_rn(z[1], r1);
    ob[2 * HW] = __fadd_rn(z[2], r2);
    ob[3 * HW] = __fadd_rn(z[3], r3);

    float acc = sumsq4(r0, r1, r2, r3);

    // warp shuffle reduce, then one smem round (deterministic order)
#pragma unroll
    for (int o = 16; o > 0; o >>= 1)
        acc += __shfl_down_sync(0xffffffffu, acc, o);
    if ((threadIdx.x & 31) == 0) wsum[threadIdx.x >> 5] = acc;
    __syncthreads();
    if (threadIdx.x == 0) {
        float t = 0.f;
#pragma unroll
        for (int w = 0; w < FT / 32; w++) t += wsum[w];
        g_partial[blockIdx.x] = t;
        __threadfence();
        islast = (atomicAdd(&g_ctr, 1) == FBLOCKS - 1);
    }
    __syncthreads();

    if (islast) {
        // final reduction over FBLOCKS=128 partials (fixed tree order);
        // red[] has FBLOCKS entries, block has FT threads — keep guards.
        __shared__ float red[FBLOCKS];
        if (threadIdx.x < FBLOCKS) red[threadIdx.x] = g_partial[threadIdx.x];
        __syncthreads();
#pragma unroll
        for (int st = FBLOCKS / 2; st > 0; st >>= 1) {
            if (threadIdx.x < st) red[threadIdx.x] += red[threadIdx.x + st];
            __syncthreads();
        }
        if (threadIdx.x == 0) {
            out[loss_idx] = red[0] * (1.25f / (float)(NPOINTS * 4));
            g_ctr = 0;   // restore invariant for next replay
        }
    }
}

extern "C" void kernel_launch(void* const* d_in, const int* in_sizes, int n_in,
                              void* d_out, int out_size)
{
    const float* zin = (const float*)d_in[0];  // z_e_in [8,4,64,64]
    const float* Wm  = (const float*)d_in[1];  // pq_w [4,4]
    const float* bv  = (const float*)d_in[2];  // pq_b [4]
    const float* cb  = (const float*)d_in[3];  // codebook [8192,4]
    float* out = (float*)d_out;

    dim3 g1(PGROUPS, NSLICE);
    vq_search<<<g1, T1>>>(zin, Wm, bv, cb);
    vq_finalize<<<FBLOCKS, FT>>>(zin, Wm, bv, cb, out, out_size - 1);
}